// round 2
// baseline (speedup 1.0000x reference)
#include <cuda_runtime.h>
#include <cstdint>

#define L_SEQ   1024
#define BATCH   256
#define LB      (L_SEQ*BATCH)
#define KV      10648
#define NFRAG   32
#define KLEN    96
#define ROWS3L  (3*L_SEQ)

typedef unsigned long long ull;

// ---------------- device scratch ----------------
__device__ float4 g_Tk4[KV*16];            // kmer-fused table (10648 x 64)
__device__ float4 g_Ts4[20*16];            // seq-fused table (+b0)
__device__ float  g_ct[(size_t)ROWS3L*BATCH*3];  // c_tilde / frag (in place)
__device__ __align__(16) float g_R[NFRAG*BATCH*12]; // per (f,b): R cols + trans
__device__ int    g_seq[LB];
__device__ int    g_kmer[LB];
__device__ int    g_flag[2];

// ---------------- f32x2 helpers ----------------
__device__ __forceinline__ ull pk2(float x, float y){
    ull r; asm("mov.b64 %0,{%1,%2};" : "=l"(r) : "f"(x), "f"(y)); return r;
}
__device__ __forceinline__ float2 up2(ull a){
    float x,y; asm("mov.b64 {%0,%1},%2;" : "=f"(x), "=f"(y) : "l"(a));
    return make_float2(x,y);
}
__device__ __forceinline__ ull fma2(ull a, ull b, ull c){
    ull d; asm("fma.rn.f32x2 %0,%1,%2,%3;" : "=l"(d) : "l"(a), "l"(b), "l"(c));
    return d;
}
__device__ __forceinline__ ull shflx1(ull v){
    unsigned lo = (unsigned)v, hi = (unsigned)(v >> 32);
    lo = __shfl_xor_sync(0xffffffffu, lo, 1);
    hi = __shfl_xor_sync(0xffffffffu, hi, 1);
    return ((ull)hi << 32) | (ull)lo;
}

// ---------------- dtype detect (int64 vs int32) ----------------
__global__ void k_detect(const int* __restrict__ s, const int* __restrict__ k){
    __shared__ int a0, a1;
    if (threadIdx.x == 0){ a0 = 0; a1 = 0; }
    __syncthreads();
    int a = 0, b = 0;
    for (int i = threadIdx.x; i < 4096; i += 256){ a |= s[2*i+1]; b |= k[2*i+1]; }
    if (a) atomicOr(&a0, 1);
    if (b) atomicOr(&a1, 1);
    __syncthreads();
    if (threadIdx.x == 0){ g_flag[0] = a0 ? 0 : 1; g_flag[1] = a1 ? 0 : 1; }
}
__global__ void k_conv(const int* __restrict__ s, const int* __restrict__ k){
    int f0 = g_flag[0], f1 = g_flag[1];
    for (int i = blockIdx.x*blockDim.x + threadIdx.x; i < LB; i += gridDim.x*blockDim.x){
        g_seq[i]  = f0 ? s[2*i] : s[i];
        g_kmer[i] = f1 ? k[2*i] : k[i];
    }
}

// ---------------- Ts table: seq_embed @ W0[0:16] + b0 ----------------
__global__ void k_ts(const float* __restrict__ se, const float* __restrict__ W0,
                     const float* __restrict__ b0){
    int c = threadIdx.x;  // 64
    float* Ts = (float*)g_Ts4;
    for (int s = 0; s < 20; s++){
        float a = b0[c];
        #pragma unroll
        for (int j = 0; j < 16; j++) a += se[s*16+j] * W0[j*64+c];
        Ts[s*64+c] = a;
    }
}

// ---------------- Tk table: kmer_embed @ W0[16:272] ----------------
__global__ __launch_bounds__(256) void k_tk(const float* __restrict__ ke,
                                            const float* __restrict__ W0){
    __shared__ float rows[32*256];
    __shared__ float wt[32*64];
    int tid = threadIdx.x;
    int R0 = blockIdx.x * 32;
    for (int i = tid; i < 32*256; i += 256){
        int r = i >> 8, jj = i & 255;
        int gr = R0 + r;
        rows[i] = (gr < KV) ? ke[(size_t)gr*256 + jj] : 0.f;
    }
    int rg = tid >> 6, c = tid & 63;
    float acc[8];
    #pragma unroll
    for (int rr = 0; rr < 8; rr++) acc[rr] = 0.f;
    for (int jt = 0; jt < 8; jt++){
        __syncthreads();
        for (int i = tid; i < 32*64; i += 256){
            int j = i >> 6, cc = i & 63;
            wt[i] = W0[(16 + jt*32 + j)*64 + cc];
        }
        __syncthreads();
        #pragma unroll 4
        for (int j = 0; j < 32; j++){
            float w = wt[j*64 + c];
            int jj = jt*32 + j;
            #pragma unroll
            for (int rr = 0; rr < 8; rr++)
                acc[rr] += rows[(rg*8+rr)*256 + jj] * w;
        }
    }
    float* Tk = (float*)g_Tk4;
    #pragma unroll
    for (int rr = 0; rr < 8; rr++){
        int gr = R0 + rg*8 + rr;
        if (gr < KV) Tk[gr*64 + c] = acc[rr];
    }
}

// ---------------- main fused MLP (f32x2 packed) ----------------
// 128 threads/block, 64 token-pairs/block (128 tokens). Thread (p,half):
// tokens t0,t0+1 packed in f32x2, columns [half*32, half*32+32).
#define SME_WE2 0
#define SME_W0P 4096
#define SME_W1P 5440
#define SME_BE2 6208
#define SME_PSH 6272
#define SME_BYTES (6272*8 + 2688*4)

__global__ __launch_bounds__(128,3) void k_mlp(const float* __restrict__ pssm,
        const float* __restrict__ W0, const float* __restrict__ We,
        const float* __restrict__ be, const float* __restrict__ W1,
        const float* __restrict__ b1){
    extern __shared__ ull sm[];
    ull* we2 = sm + SME_WE2;
    ull* w0p = sm + SME_W0P;
    ull* w1p = sm + SME_W1P;
    ull* be2 = sm + SME_BE2;
    float* psh = (float*)(sm + SME_PSH);
    __shared__ float b1s[9];
    int tid = threadIdx.x, blk = blockIdx.x;

    #pragma unroll 4
    for (int i = tid; i < 4096; i += 128){ float w = We[i]; we2[i] = pk2(w,w); }
    for (int i = tid; i < 1344; i += 128){
        int j = i >> 6, c = i & 63;
        float w = W0[(272+j)*64 + c];
        w0p[i] = pk2(w,w);
    }
    for (int i = tid; i < 576; i += 128){
        int j = i/9, o = i - j*9;
        float w = W1[i];
        w1p[j*12+o] = pk2(w,w);
    }
    if (tid < 64){ float x = be[tid]; be2[tid] = pk2(x,x); }
    if (tid >= 64 && tid < 73) b1s[tid-64] = b1[tid-64];
    for (int i = tid; i < 2688; i += 128) psh[i] = pssm[(size_t)blk*2688 + i];
    __syncthreads();

    int p = tid >> 1, half = tid & 1;
    int t0 = blk*128 + (p << 1);
    int cb = half << 5;
    int s0 = g_seq[t0],  s1 = g_seq[t0+1];
    int k0 = g_kmer[t0], k1 = g_kmer[t0+1];

    ull acc[32];
    // init: Ts[seq] + Tk[kmer] (own 32 cols, both tokens)
    #pragma unroll
    for (int q = 0; q < 8; q++){
        float4 ta = g_Tk4[k0*16 + (half<<3) + q];
        float4 tb = g_Tk4[k1*16 + (half<<3) + q];
        float4 sa = g_Ts4[s0*16 + (half<<3) + q];
        float4 sb = g_Ts4[s1*16 + (half<<3) + q];
        acc[q*4+0] = pk2(ta.x+sa.x, tb.x+sb.x);
        acc[q*4+1] = pk2(ta.y+sa.y, tb.y+sb.y);
        acc[q*4+2] = pk2(ta.z+sa.z, tb.z+sb.z);
        acc[q*4+3] = pk2(ta.w+sa.w, tb.w+sb.w);
    }
    // pssm @ W0[272:293]
    const float* ps0 = psh + (p << 1)*21;
    #pragma unroll
    for (int j = 0; j < 21; j++){
        ull pj = pk2(ps0[j], ps0[21+j]);
        const ulonglong2* wr = (const ulonglong2*)(w0p + j*64 + cb);
        #pragma unroll
        for (int cc = 0; cc < 16; cc++){
            ulonglong2 ww = wr[cc];
            acc[cc*2]   = fma2(pj, ww.x, acc[cc*2]);
            acc[cc*2+1] = fma2(pj, ww.y, acc[cc*2+1]);
        }
    }
    ull h[32];
    #pragma unroll
    for (int c = 0; c < 32; c++) h[c] = acc[c];  // layer0 output, no relu

    // two relu(h@We+be) layers, same We
    #pragma unroll 1
    for (int LL = 0; LL < 2; LL++){
        #pragma unroll
        for (int c = 0; c < 32; c++) acc[c] = be2[cb + c];
        #pragma unroll
        for (int ph = 0; ph < 2; ph++){
            int jb = ((half ^ ph) << 5);
            #pragma unroll
            for (int jl = 0; jl < 32; jl++){
                ull hj = h[jl];
                if (ph) hj = shflx1(hj);   // partner's h half
                const ulonglong2* wr = (const ulonglong2*)(we2 + (jb+jl)*64 + cb);
                #pragma unroll
                for (int cc = 0; cc < 16; cc++){
                    ulonglong2 ww = wr[cc];
                    acc[cc*2]   = fma2(hj, ww.x, acc[cc*2]);
                    acc[cc*2+1] = fma2(hj, ww.y, acc[cc*2+1]);
                }
            }
        }
        #pragma unroll
        for (int c = 0; c < 32; c++){
            float2 f = up2(acc[c]);
            h[c] = pk2(fmaxf(f.x, 0.f), fmaxf(f.y, 0.f));
        }
    }

    // final 64->9 (each thread partial over its 32 j's, combine via shfl)
    ull op[9];
    #pragma unroll
    for (int o = 0; o < 9; o++) op[o] = pk2(0.f, 0.f);
    #pragma unroll
    for (int jl = 0; jl < 32; jl++){
        ull hj = h[jl];
        const ull* wr = w1p + ((half<<5)+jl)*12;
        #pragma unroll
        for (int o = 0; o < 9; o++) op[o] = fma2(hj, wr[o], op[o]);
    }
    int t = t0 + half;
    int l = t >> 8, bb = t & 255;
    #pragma unroll
    for (int o = 0; o < 9; o++){
        ull other = shflx1(op[o]);
        float2 m = up2(op[o]), q = up2(other);
        float lo = m.x + q.x + b1s[o];
        float hi = m.y + q.y + b1s[o];
        float val = half ? hi : lo;
        int r = o/3, j3 = o - r*3;
        g_ct[((size_t)(3*l + r)*256 + bb)*3 + j3] = val;
    }
}

// ---------------- fragment NeRF scan (in place over g_ct) ----------------
__global__ __launch_bounds__(256) void k_frag(){
    int tid = blockIdx.x*256 + threadIdx.x;  // 0..8191
    int b = tid & 255, f = tid >> 8;
    float pax = -0.70710678118654752f, pay = 1.22474487139158905f, paz = 0.f;
    float pbx = -1.41421356237309505f, pby = 0.f, pbz = 0.f;
    float pcx = 0.f, pcy = 0.f, pcz = 0.f;
    float nx[2], ny[2], nz[2];
    #pragma unroll
    for (int q = 0; q < 2; q++){
        size_t id = ((size_t)(f*KLEN + q)*256 + b)*3;
        nx[q] = g_ct[id]; ny[q] = g_ct[id+1]; nz[q] = g_ct[id+2];
    }
    #pragma unroll 1
    for (int t = 0; t < KLEN; t++){
        float tx = nx[0], ty = ny[0], tz = nz[0];
        nx[0] = nx[1]; ny[0] = ny[1]; nz[0] = nz[1];
        if (t + 2 < KLEN){
            size_t id = ((size_t)(f*KLEN + t + 2)*256 + b)*3;
            nx[1] = g_ct[id]; ny[1] = g_ct[id+1]; nz[1] = g_ct[id+2];
        }
        float ux = pcx-pbx, uy = pcy-pby, uz = pcz-pbz;
        float s = rsqrtf(fmaxf(ux*ux+uy*uy+uz*uz, 1e-24f));
        ux *= s; uy *= s; uz *= s;                          // bc
        float vx = pbx-pax, vy = pby-pay, vz = pbz-paz;     // b-a
        float wx = vy*uz - vz*uy, wy = vz*ux - vx*uz, wz = vx*uy - vy*ux;
        float s2 = rsqrtf(fmaxf(wx*wx+wy*wy+wz*wz, 1e-24f));
        wx *= s2; wy *= s2; wz *= s2;                       // n
        float mx = wy*uz - wz*uy, my = wz*ux - wx*uz, mz = wx*uy - wy*ux; // n x bc
        float dx = pcx + ux*tx + mx*ty + wx*tz;
        float dy = pcy + uy*tx + my*ty + wy*tz;
        float dz = pcz + uz*tx + mz*ty + wz*tz;
        size_t od = ((size_t)(f*KLEN + t)*256 + b)*3;
        g_ct[od] = dx; g_ct[od+1] = dy; g_ct[od+2] = dz;
        pax = pbx; pay = pby; paz = pbz;
        pbx = pcx; pby = pcy; pbz = pcz;
        pcx = dx;  pcy = dy;  pcz = dz;
    }
}

// ---------------- assembly carry chain: per-batch rigid frames ----------------
__global__ void k_carry(){
    int b = threadIdx.x;  // 256
    float pax = -0.70710678118654752f, pay = 1.22474487139158905f, paz = 0.f;
    float pbx = -1.41421356237309505f, pby = 0.f, pbz = 0.f;
    float pcx = 0.f, pcy = 0.f, pcz = 0.f;
    for (int f = 0; f < NFRAG; f++){
        float ux = pcx-pbx, uy = pcy-pby, uz = pcz-pbz;
        float s = rsqrtf(fmaxf(ux*ux+uy*uy+uz*uz, 1e-24f));
        ux *= s; uy *= s; uz *= s;
        float vx = pbx-pax, vy = pby-pay, vz = pbz-paz;
        float wx = vy*uz - vz*uy, wy = vz*ux - vx*uz, wz = vx*uy - vy*ux;
        float s2 = rsqrtf(fmaxf(wx*wx+wy*wy+wz*wz, 1e-24f));
        wx *= s2; wy *= s2; wz *= s2;
        float mx = wy*uz - wz*uy, my = wz*ux - wx*uz, mz = wx*uy - wy*ux;
        float* R = g_R + ((size_t)f*256 + b)*12;
        R[0]=ux; R[1]=uy; R[2]=uz;
        R[3]=mx; R[4]=my; R[5]=mz;
        R[6]=wx; R[7]=wy; R[8]=wz;
        R[9]=pcx; R[10]=pcy; R[11]=pcz;
        float yx[3], yy[3], yz[3];
        #pragma unroll
        for (int i = 0; i < 3; i++){
            size_t id = ((size_t)(f*KLEN + 93 + i)*256 + b)*3;
            float px = g_ct[id], py = g_ct[id+1], pz = g_ct[id+2];
            yx[i] = pcx + ux*px + mx*py + wx*pz;
            yy[i] = pcy + uy*px + my*py + wy*pz;
            yz[i] = pcz + uz*px + mz*py + wz*pz;
        }
        pax = yx[0]; pay = yy[0]; paz = yz[0];
        pbx = yx[1]; pby = yy[1]; pbz = yz[1];
        pcx = yx[2]; pcy = yy[2]; pcz = yz[2];
    }
}

// ---------------- apply rigid transforms to all points ----------------
__global__ __launch_bounds__(256) void k_apply(float* __restrict__ out){
    int t = blockIdx.x;   // 0..95
    int f = blockIdx.y;   // 0..31
    int b = threadIdx.x;
    const float4* R4 = (const float4*)g_R;
    float4 q0 = R4[(f*256 + b)*3 + 0];
    float4 q1 = R4[(f*256 + b)*3 + 1];
    float4 q2 = R4[(f*256 + b)*3 + 2];
    size_t id = ((size_t)(f*KLEN + t)*256 + b)*3;
    float px = g_ct[id], py = g_ct[id+1], pz = g_ct[id+2];
    // q0=(ux,uy,uz,mx) q1=(my,mz,wx,wy) q2=(wz,cx,cy,cz)
    out[id]   = q2.y + q0.x*px + q0.w*py + q1.z*pz;
    out[id+1] = q2.z + q0.y*px + q1.x*py + q1.w*pz;
    out[id+2] = q2.w + q0.z*px + q1.y*py + q2.x*pz;
}

extern "C" void kernel_launch(void* const* d_in, const int* in_sizes, int n_in,
                              void* d_out, int out_size){
    const int*   seq  = (const int*)d_in[0];
    const int*   kmer = (const int*)d_in[1];
    const float* pssm = (const float*)d_in[2];
    // d_in[3] = length (unused by reference)
    const float* se   = (const float*)d_in[4];
    const float* ke   = (const float*)d_in[5];
    const float* W0   = (const float*)d_in[6];
    const float* b0   = (const float*)d_in[7];
    const float* We   = (const float*)d_in[8];
    const float* be   = (const float*)d_in[9];
    const float* W1   = (const float*)d_in[10];
    const float* b1   = (const float*)d_in[11];

    cudaFuncSetAttribute(k_mlp, cudaFuncAttributeMaxDynamicSharedMemorySize, SME_BYTES);

    k_detect<<<1,256>>>(seq, kmer);
    k_conv<<<264,256>>>(seq, kmer);
    k_ts<<<1,64>>>(se, W0, b0);
    k_tk<<<(KV+31)/32,256>>>(ke, W0);
    k_mlp<<<LB/128,128,SME_BYTES>>>(pssm, W0, We, be, W1, b1);
    k_frag<<<32,256>>>();
    k_carry<<<1,256>>>();
    dim3 ga(96, 32);
    k_apply<<<ga,256>>>((float*)d_out);
}

// round 3
// speedup vs baseline: 1.5415x; 1.5415x over previous
#include <cuda_runtime.h>
#include <cstdint>

#define L_SEQ   1024
#define BATCH   256
#define LB      (L_SEQ*BATCH)
#define KV      10648
#define NFRAG   32
#define KLEN    96
#define ROWS3L  (3*L_SEQ)

typedef unsigned long long ull;

// ---------------- device scratch ----------------
__device__ float4 g_Tk4[KV*16];            // kmer-fused table (10648 x 64)
__device__ float4 g_Ts4[20*16];            // seq-fused table (+b0)
__device__ float  g_ct[(size_t)ROWS3L*BATCH*3];  // c_tilde / frag (in place)
__device__ __align__(16) float g_R[NFRAG*BATCH*12];
__device__ int    g_seq[LB];
__device__ int    g_kmer[LB];
__device__ int    g_flag[2];

// ---------------- f32x2 helpers ----------------
__device__ __forceinline__ ull pk2(float x, float y){
    ull r; asm("mov.b64 %0,{%1,%2};" : "=l"(r) : "f"(x), "f"(y)); return r;
}
__device__ __forceinline__ float2 up2(ull a){
    float x,y; asm("mov.b64 {%0,%1},%2;" : "=f"(x), "=f"(y) : "l"(a));
    return make_float2(x,y);
}
__device__ __forceinline__ ull fma2(ull a, ull b, ull c){
    ull d; asm("fma.rn.f32x2 %0,%1,%2,%3;" : "=l"(d) : "l"(a), "l"(b), "l"(c));
    return d;
}
__device__ __forceinline__ ull add2(ull a, ull b){
    ull d; asm("add.rn.f32x2 %0,%1,%2;" : "=l"(d) : "l"(a), "l"(b));
    return d;
}
__device__ __forceinline__ ull shflx(ull v, int m){
    unsigned lo = (unsigned)v, hi = (unsigned)(v >> 32);
    lo = __shfl_xor_sync(0xffffffffu, lo, m);
    hi = __shfl_xor_sync(0xffffffffu, hi, m);
    return ((ull)hi << 32) | (ull)lo;
}

// ---------------- dtype detect (int64 vs int32) ----------------
__global__ void k_detect(const int* __restrict__ s, const int* __restrict__ k){
    __shared__ int a0, a1;
    if (threadIdx.x == 0){ a0 = 0; a1 = 0; }
    __syncthreads();
    int a = 0, b = 0;
    for (int i = threadIdx.x; i < 4096; i += 256){ a |= s[2*i+1]; b |= k[2*i+1]; }
    if (a) atomicOr(&a0, 1);
    if (b) atomicOr(&a1, 1);
    __syncthreads();
    if (threadIdx.x == 0){ g_flag[0] = a0 ? 0 : 1; g_flag[1] = a1 ? 0 : 1; }
}
__global__ void k_conv(const int* __restrict__ s, const int* __restrict__ k){
    int f0 = g_flag[0], f1 = g_flag[1];
    for (int i = blockIdx.x*blockDim.x + threadIdx.x; i < LB; i += gridDim.x*blockDim.x){
        g_seq[i]  = f0 ? s[2*i] : s[i];
        g_kmer[i] = f1 ? k[2*i] : k[i];
    }
}

// ---------------- Ts table: seq_embed @ W0[0:16] + b0 ----------------
__global__ void k_ts(const float* __restrict__ se, const float* __restrict__ W0,
                     const float* __restrict__ b0){
    int c = threadIdx.x;
    float* Ts = (float*)g_Ts4;
    for (int s = 0; s < 20; s++){
        float a = b0[c];
        #pragma unroll
        for (int j = 0; j < 16; j++) a += se[s*16+j] * W0[j*64+c];
        Ts[s*64+c] = a;
    }
}

// ---------------- Tk table: kmer_embed @ W0[16:272] (f32x2 packed) --------
// 32 rows (16 packed pairs) per block, 256 threads: rg=tid>>6 owns 4 pairs, c=tid&63.
__global__ __launch_bounds__(256) void k_tk(const float* __restrict__ ke,
                                            const float* __restrict__ W0){
    extern __shared__ ull smtk[];
    ull* rp  = smtk;          // 16 pairs x 256 j  = 4096 ull (32KB)
    ull* wt2 = smtk + 4096;   // 16 jpairs x 128   = 2048 ull (16KB)
    float* rpf = (float*)rp;
    int tid = threadIdx.x;
    int R0 = blockIdx.x * 32;
    for (int i = tid; i < 8192; i += 256){
        int r = i >> 8, j = i & 255;
        int gr = R0 + r;
        float v = (gr < KV) ? ke[(size_t)gr*256 + j] : 0.f;
        rpf[(r>>1)*512 + j*2 + (r&1)] = v;
    }
    int rg = tid >> 6, c = tid & 63;
    ull acc[4];
    #pragma unroll
    for (int pr = 0; pr < 4; pr++) acc[pr] = pk2(0.f, 0.f);
    for (int jt = 0; jt < 8; jt++){
        __syncthreads();
        for (int i = tid; i < 2048; i += 256){
            int j = i >> 6, cc = i & 63;
            float w = W0[(16 + jt*32 + j)*64 + cc];
            wt2[(j>>1)*128 + cc*2 + (j&1)] = pk2(w, w);
        }
        __syncthreads();
        #pragma unroll 4
        for (int j2 = 0; j2 < 16; j2++){
            ulonglong2 w2 = *(const ulonglong2*)(wt2 + j2*128 + (c<<1));
            int jbase = jt*32 + j2*2;
            #pragma unroll
            for (int pr = 0; pr < 4; pr++){
                ulonglong2 r2 = *(const ulonglong2*)(rp + (rg*4+pr)*256 + jbase);
                acc[pr] = fma2(r2.x, w2.x, acc[pr]);
                acc[pr] = fma2(r2.y, w2.y, acc[pr]);
            }
        }
    }
    float* Tk = (float*)g_Tk4;
    #pragma unroll
    for (int pr = 0; pr < 4; pr++){
        int gr = R0 + rg*8 + 2*pr;
        float2 f = up2(acc[pr]);
        if (gr < KV)     Tk[(size_t)gr*64 + c]     = f.x;
        if (gr + 1 < KV) Tk[(size_t)(gr+1)*64 + c] = f.y;
    }
}

// ---------------- main fused MLP (f32x2, quarter-split columns) ----------
// 128 threads/block, 8 tiles of 128 tokens each. Thread (g=tid>>2, qd=tid&3):
// 4 tokens = 2 f32x2 pairs, 16 columns [qd*16, qd*16+16).
// Skewed smem layouts kill the 4-way quarter bank conflicts.
#define TILES 8
#define OWE 0                          // We dup-packed: j*72 + c + (c>>4)*2
#define OW0 4608                       // W0[272:293]:    j*72 + c + (c>>4)*2
#define OW1 6120                       // W1:             j*12 + (j>>4)*2 + o
#define OBE 6904                       // be:             c + (c>>4)*2
#define OH2 6976                       // h pairs: pair*71 + c + (c>>4)*2
#define OPS 11520                      // pssm floats (2688)
#define SMEU 12864
#define SME_BYTES (SMEU*8)

__global__ __launch_bounds__(128,2) void k_mlp(const float* __restrict__ pssm,
        const float* __restrict__ W0, const float* __restrict__ We,
        const float* __restrict__ be, const float* __restrict__ W1,
        const float* __restrict__ b1){
    extern __shared__ ull sm[];
    ull* we2 = sm + OWE;
    ull* w0p = sm + OW0;
    ull* w1p = sm + OW1;
    ull* be2 = sm + OBE;
    ull* h2  = sm + OH2;
    float* psh = (float*)(sm + OPS);
    __shared__ float b1s[9];
    int tid = threadIdx.x, blk = blockIdx.x;

    #pragma unroll 4
    for (int i = tid; i < 4096; i += 128){
        int j = i >> 6, c = i & 63;
        float w = We[i];
        we2[j*72 + c + ((c>>4)<<1)] = pk2(w, w);
    }
    for (int i = tid; i < 1344; i += 128){
        int j = i >> 6, c = i & 63;
        float w = W0[(272+j)*64 + c];
        w0p[j*72 + c + ((c>>4)<<1)] = pk2(w, w);
    }
    for (int i = tid; i < 576; i += 128){
        int j = i/9, o = i - j*9;
        float w = W1[i];
        w1p[j*12 + ((j>>4)<<1) + o] = pk2(w, w);
    }
    if (tid < 64){ float x = be[tid]; be2[tid + ((tid>>4)<<1)] = pk2(x, x); }
    if (tid >= 64 && tid < 73) b1s[tid-64] = b1[tid-64];

    int g = tid >> 2, qd = tid & 3;
    int cbs = qd*18;
    ull* hA = h2 + g*142;
    ull* hB = hA + 71;

    for (int it = 0; it < TILES; it++){
        int tile = blk*TILES + it;
        __syncthreads();
        for (int i = tid; i < 2688; i += 128) psh[i] = pssm[(size_t)tile*2688 + i];
        __syncthreads();

        int t0 = tile*128 + g*4;
        int s0 = g_seq[t0],  s1 = g_seq[t0+1],  s2 = g_seq[t0+2],  s3 = g_seq[t0+3];
        int k0 = g_kmer[t0], k1 = g_kmer[t0+1], k2 = g_kmer[t0+2], k3 = g_kmer[t0+3];

        ull accA[16], accB[16];
        #pragma unroll
        for (int q = 0; q < 4; q++){
            int o = (qd<<2) + q;
            float4 a0 = g_Tk4[k0*16+o], a1 = g_Tk4[k1*16+o];
            float4 e0 = g_Ts4[s0*16+o], e1 = g_Ts4[s1*16+o];
            accA[q*4+0] = pk2(a0.x+e0.x, a1.x+e1.x);
            accA[q*4+1] = pk2(a0.y+e0.y, a1.y+e1.y);
            accA[q*4+2] = pk2(a0.z+e0.z, a1.z+e1.z);
            accA[q*4+3] = pk2(a0.w+e0.w, a1.w+e1.w);
            float4 c0 = g_Tk4[k2*16+o], c1 = g_Tk4[k3*16+o];
            float4 f0 = g_Ts4[s2*16+o], f1 = g_Ts4[s3*16+o];
            accB[q*4+0] = pk2(c0.x+f0.x, c1.x+f1.x);
            accB[q*4+1] = pk2(c0.y+f0.y, c1.y+f1.y);
            accB[q*4+2] = pk2(c0.z+f0.z, c1.z+f1.z);
            accB[q*4+3] = pk2(c0.w+f0.w, c1.w+f1.w);
        }
        const float* pp = psh + g*84;
        #pragma unroll 3
        for (int j = 0; j < 21; j++){
            ull pjA = pk2(pp[j],    pp[21+j]);
            ull pjB = pk2(pp[42+j], pp[63+j]);
            const ulonglong2* wr = (const ulonglong2*)(w0p + j*72 + cbs);
            #pragma unroll
            for (int cc = 0; cc < 8; cc++){
                ulonglong2 ww = wr[cc];
                accA[2*cc]   = fma2(pjA, ww.x, accA[2*cc]);
                accA[2*cc+1] = fma2(pjA, ww.y, accA[2*cc+1]);
                accB[2*cc]   = fma2(pjB, ww.x, accB[2*cc]);
                accB[2*cc+1] = fma2(pjB, ww.y, accB[2*cc+1]);
            }
        }
        // layer0 output (no relu) -> h2
        #pragma unroll
        for (int i = 0; i < 16; i++){ hA[cbs+i] = accA[i]; hB[cbs+i] = accB[i]; }
        __syncwarp();

        #pragma unroll 1
        for (int LL = 0; LL < 2; LL++){
            #pragma unroll
            for (int i = 0; i < 16; i++){
                ull bv = be2[cbs+i];
                accA[i] = bv; accB[i] = bv;
            }
            #pragma unroll 8
            for (int j = 0; j < 64; j++){
                int js = j + ((j>>4)<<1);
                ull hjA = hA[js], hjB = hB[js];
                const ulonglong2* wr = (const ulonglong2*)(we2 + j*72 + cbs);
                #pragma unroll
                for (int cc = 0; cc < 8; cc++){
                    ulonglong2 ww = wr[cc];
                    accA[2*cc]   = fma2(hjA, ww.x, accA[2*cc]);
                    accA[2*cc+1] = fma2(hjA, ww.y, accA[2*cc+1]);
                    accB[2*cc]   = fma2(hjB, ww.x, accB[2*cc]);
                    accB[2*cc+1] = fma2(hjB, ww.y, accB[2*cc+1]);
                }
            }
            #pragma unroll
            for (int i = 0; i < 16; i++){
                float2 fa = up2(accA[i]);
                accA[i] = pk2(fmaxf(fa.x,0.f), fmaxf(fa.y,0.f));
                float2 fb = up2(accB[i]);
                accB[i] = pk2(fmaxf(fb.x,0.f), fmaxf(fb.y,0.f));
            }
            if (LL == 0){
                __syncwarp();
                #pragma unroll
                for (int i = 0; i < 16; i++){ hA[cbs+i] = accA[i]; hB[cbs+i] = accB[i]; }
                __syncwarp();
            }
        }

        // final 64->9: partial over own 16 j's, butterfly-reduce in 4-lane group
        int t_mine = t0 + qd;
        int l = t_mine >> 8, bb = t_mine & 255;
        {
            ull opA[9];
            #pragma unroll
            for (int o = 0; o < 9; o++) opA[o] = pk2(0.f, 0.f);
            #pragma unroll
            for (int jl = 0; jl < 16; jl++){
                const ull* wr = w1p + qd*194 + jl*12;
                ull ha = accA[jl];
                #pragma unroll
                for (int o = 0; o < 9; o++) opA[o] = fma2(ha, wr[o], opA[o]);
            }
            #pragma unroll
            for (int o = 0; o < 9; o++){
                opA[o] = add2(opA[o], shflx(opA[o], 1));
                opA[o] = add2(opA[o], shflx(opA[o], 2));
            }
            if (qd < 2){
                #pragma unroll
                for (int o = 0; o < 9; o++){
                    float2 v = up2(opA[o]);
                    float val = ((qd & 1) ? v.y : v.x) + b1s[o];
                    int r = o/3, j3 = o - r*3;
                    g_ct[((size_t)(3*l + r)*256 + bb)*3 + j3] = val;
                }
            }
        }
        {
            ull opB[9];
            #pragma unroll
            for (int o = 0; o < 9; o++) opB[o] = pk2(0.f, 0.f);
            #pragma unroll
            for (int jl = 0; jl < 16; jl++){
                const ull* wr = w1p + qd*194 + jl*12;
                ull hb = accB[jl];
                #pragma unroll
                for (int o = 0; o < 9; o++) opB[o] = fma2(hb, wr[o], opB[o]);
            }
            #pragma unroll
            for (int o = 0; o < 9; o++){
                opB[o] = add2(opB[o], shflx(opB[o], 1));
                opB[o] = add2(opB[o], shflx(opB[o], 2));
            }
            if (qd >= 2){
                #pragma unroll
                for (int o = 0; o < 9; o++){
                    float2 v = up2(opB[o]);
                    float val = ((qd & 1) ? v.y : v.x) + b1s[o];
                    int r = o/3, j3 = o - r*3;
                    g_ct[((size_t)(3*l + r)*256 + bb)*3 + j3] = val;
                }
            }
        }
    }
}

// ---------------- fragment NeRF scan (in place over g_ct) ----------------
__global__ __launch_bounds__(256) void k_frag(){
    int tid = blockIdx.x*256 + threadIdx.x;
    int b = tid & 255, f = tid >> 8;
    float pax = -0.70710678118654752f, pay = 1.22474487139158905f, paz = 0.f;
    float pbx = -1.41421356237309505f, pby = 0.f, pbz = 0.f;
    float pcx = 0.f, pcy = 0.f, pcz = 0.f;
    float nx[2], ny[2], nz[2];
    #pragma unroll
    for (int q = 0; q < 2; q++){
        size_t id = ((size_t)(f*KLEN + q)*256 + b)*3;
        nx[q] = g_ct[id]; ny[q] = g_ct[id+1]; nz[q] = g_ct[id+2];
    }
    #pragma unroll 1
    for (int t = 0; t < KLEN; t++){
        float tx = nx[0], ty = ny[0], tz = nz[0];
        nx[0] = nx[1]; ny[0] = ny[1]; nz[0] = nz[1];
        if (t + 2 < KLEN){
            size_t id = ((size_t)(f*KLEN + t + 2)*256 + b)*3;
            nx[1] = g_ct[id]; ny[1] = g_ct[id+1]; nz[1] = g_ct[id+2];
        }
        float ux = pcx-pbx, uy = pcy-pby, uz = pcz-pbz;
        float s = rsqrtf(fmaxf(ux*ux+uy*uy+uz*uz, 1e-24f));
        ux *= s; uy *= s; uz *= s;
        float vx = pbx-pax, vy = pby-pay, vz = pbz-paz;
        float wx = vy*uz - vz*uy, wy = vz*ux - vx*uz, wz = vx*uy - vy*ux;
        float s2 = rsqrtf(fmaxf(wx*wx+wy*wy+wz*wz, 1e-24f));
        wx *= s2; wy *= s2; wz *= s2;
        float mx = wy*uz - wz*uy, my = wz*ux - wx*uz, mz = wx*uy - wy*ux;
        float dx = pcx + ux*tx + mx*ty + wx*tz;
        float dy = pcy + uy*tx + my*ty + wy*tz;
        float dz = pcz + uz*tx + mz*ty + wz*tz;
        size_t od = ((size_t)(f*KLEN + t)*256 + b)*3;
        g_ct[od] = dx; g_ct[od+1] = dy; g_ct[od+2] = dz;
        pax = pbx; pay = pby; paz = pbz;
        pbx = pcx; pby = pcy; pbz = pcz;
        pcx = dx;  pcy = dy;  pcz = dz;
    }
}

// ---------------- assembly carry chain ----------------
__global__ void k_carry(){
    int b = threadIdx.x;
    float pax = -0.70710678118654752f, pay = 1.22474487139158905f, paz = 0.f;
    float pbx = -1.41421356237309505f, pby = 0.f, pbz = 0.f;
    float pcx = 0.f, pcy = 0.f, pcz = 0.f;
    for (int f = 0; f < NFRAG; f++){
        float ux = pcx-pbx, uy = pcy-pby, uz = pcz-pbz;
        float s = rsqrtf(fmaxf(ux*ux+uy*uy+uz*uz, 1e-24f));
        ux *= s; uy *= s; uz *= s;
        float vx = pbx-pax, vy = pby-pay, vz = pbz-paz;
        float wx = vy*uz - vz*uy, wy = vz*ux - vx*uz, wz = vx*uy - vy*ux;
        float s2 = rsqrtf(fmaxf(wx*wx+wy*wy+wz*wz, 1e-24f));
        wx *= s2; wy *= s2; wz *= s2;
        float mx = wy*uz - wz*uy, my = wz*ux - wx*uz, mz = wx*uy - wy*ux;
        float* R = g_R + ((size_t)f*256 + b)*12;
        R[0]=ux; R[1]=uy; R[2]=uz;
        R[3]=mx; R[4]=my; R[5]=mz;
        R[6]=wx; R[7]=wy; R[8]=wz;
        R[9]=pcx; R[10]=pcy; R[11]=pcz;
        float yx[3], yy[3], yz[3];
        #pragma unroll
        for (int i = 0; i < 3; i++){
            size_t id = ((size_t)(f*KLEN + 93 + i)*256 + b)*3;
            float px = g_ct[id], py = g_ct[id+1], pz = g_ct[id+2];
            yx[i] = pcx + ux*px + mx*py + wx*pz;
            yy[i] = pcy + uy*px + my*py + wy*pz;
            yz[i] = pcz + uz*px + mz*py + wz*pz;
        }
        pax = yx[0]; pay = yy[0]; paz = yz[0];
        pbx = yx[1]; pby = yy[1]; pbz = yz[1];
        pcx = yx[2]; pcy = yy[2]; pcz = yz[2];
    }
}

// ---------------- apply rigid transforms ----------------
__global__ __launch_bounds__(256) void k_apply(float* __restrict__ out){
    int t = blockIdx.x;
    int f = blockIdx.y;
    int b = threadIdx.x;
    const float4* R4 = (const float4*)g_R;
    float4 q0 = R4[(f*256 + b)*3 + 0];
    float4 q1 = R4[(f*256 + b)*3 + 1];
    float4 q2 = R4[(f*256 + b)*3 + 2];
    size_t id = ((size_t)(f*KLEN + t)*256 + b)*3;
    float px = g_ct[id], py = g_ct[id+1], pz = g_ct[id+2];
    out[id]   = q2.y + q0.x*px + q0.w*py + q1.z*pz;
    out[id+1] = q2.z + q0.y*px + q1.x*py + q1.w*pz;
    out[id+2] = q2.w + q0.z*px + q1.y*py + q2.x*pz;
}

extern "C" void kernel_launch(void* const* d_in, const int* in_sizes, int n_in,
                              void* d_out, int out_size){
    const int*   seq  = (const int*)d_in[0];
    const int*   kmer = (const int*)d_in[1];
    const float* pssm = (const float*)d_in[2];
    const float* se   = (const float*)d_in[4];
    const float* ke   = (const float*)d_in[5];
    const float* W0   = (const float*)d_in[6];
    const float* b0   = (const float*)d_in[7];
    const float* We   = (const float*)d_in[8];
    const float* be   = (const float*)d_in[9];
    const float* W1   = (const float*)d_in[10];
    const float* b1   = (const float*)d_in[11];

    cudaFuncSetAttribute(k_mlp, cudaFuncAttributeMaxDynamicSharedMemorySize, SME_BYTES);

    k_detect<<<1,256>>>(seq, kmer);
    k_conv<<<264,256>>>(seq, kmer);
    k_ts<<<1,64>>>(se, W0, b0);
    k_tk<<<(KV+31)/32,256,49152>>>(ke, W0);
    k_mlp<<<256,128,SME_BYTES>>>(pssm, W0, We, be, W1, b1);
    k_frag<<<32,256>>>();
    k_carry<<<1,256>>>();
    dim3 ga(96, 32);
    k_apply<<<ga,256>>>((float*)d_out);
}